// round 6
// baseline (speedup 1.0000x reference)
#include <cuda_runtime.h>
#include <cuda_bf16.h>
#include <cstdint>

// ---------------------------------------------------------------------------
// Problem constants (fixed shapes per reference)
// ---------------------------------------------------------------------------
#define NE   8
#define HDIM 2048
#define FDIM 8192
#define NTOK 16384
#define CAPT (NTOK / NE)   // 2048 tokens per expert

// GEMM tiling
#define BM 256
#define BN 128
#define BK 32
#define STAGES 4
#define THREADS 512

// ---------------------------------------------------------------------------
// Scratch (static __device__ arrays; no allocation allowed)
// All "K-major" tensors below use a permuted K layout: within each 32-float
// K-block, element k is stored at position (k%4)*8 + k/4. This makes every
// mma.sync tf32 fragment a contiguous 16B ld.shared.v4.
// ---------------------------------------------------------------------------
__device__ float g_Xr [(size_t)NTOK * HDIM];            // X rounded to tf32, K-perm
__device__ float g_W1t[(size_t)NE * FDIM * HDIM];       // W1^T per expert [F,H], K-perm
__device__ float g_W2t[(size_t)NE * HDIM * FDIM];       // W2^T per expert [H,F], K-perm
__device__ float g_H  [(size_t)NTOK * FDIM];            // gelu(fc1), tf32-rounded, K-perm

// ---------------------------------------------------------------------------
// Helpers
// ---------------------------------------------------------------------------
__device__ __forceinline__ uint32_t smem_u32(const void* p) {
    uint32_t a;
    asm("{ .reg .u64 t; cvta.to.shared.u64 t, %1; cvt.u32.u64 %0, t; }" : "=r"(a) : "l"(p));
    return a;
}

__device__ __forceinline__ float to_tf32(float x) {
    uint32_t u;
    asm volatile("cvt.rna.tf32.f32 %0, %1;" : "=r"(u) : "f"(x));
    return __uint_as_float(u);
}

__device__ __forceinline__ void cp_async16(uint32_t smem_dst, const void* gmem_src) {
    asm volatile("cp.async.cg.shared.global [%0], [%1], 16;" :: "r"(smem_dst), "l"(gmem_src) : "memory");
}
__device__ __forceinline__ void cp_commit() {
    asm volatile("cp.async.commit_group;" ::: "memory");
}
template <int N>
__device__ __forceinline__ void cp_wait_group() {
    asm volatile("cp.async.wait_group %0;" :: "n"(N) : "memory");
}

// 32-bit shared-memory vector load (avoids 64-bit generic addressing ALU)
__device__ __forceinline__ void lds128(uint32_t addr, uint32_t& x, uint32_t& y,
                                       uint32_t& z, uint32_t& w) {
    asm volatile("ld.shared.v4.b32 {%0,%1,%2,%3}, [%4];"
                 : "=r"(x), "=r"(y), "=r"(z), "=r"(w) : "r"(addr));
}

// tf32 HMMA (sm_80 baseline; compiles on compute_103)
__device__ __forceinline__ void mma_tf32(float* c, uint32_t a0, uint32_t a1,
                                         uint32_t a2, uint32_t a3,
                                         uint32_t b0, uint32_t b1) {
    asm volatile(
        "mma.sync.aligned.m16n8k8.row.col.f32.tf32.tf32.f32 "
        "{%0,%1,%2,%3}, {%4,%5,%6,%7}, {%8,%9}, {%0,%1,%2,%3};"
        : "+f"(c[0]), "+f"(c[1]), "+f"(c[2]), "+f"(c[3])
        : "r"(a0), "r"(a1), "r"(a2), "r"(a3), "r"(b0), "r"(b1));
}

__device__ __forceinline__ float gelu_tanh(float x) {
    float x3 = x * x * x;
    float u  = 0.7978845608028654f * (x + 0.044715f * x3);
    return 0.5f * x * (1.0f + tanhf(u));
}

// permuted position of column/k index c within its 32-block
__device__ __forceinline__ int kperm(int c) {
    return (c & ~31) + ((c & 3) * 8) + ((c & 31) >> 2);
}

// ---------------------------------------------------------------------------
// Prep kernels
// ---------------------------------------------------------------------------
__global__ void round_permute_kernel(const float* __restrict__ src, float* __restrict__ dst,
                                     int Kq /* K/4 */, size_t n4) {
    size_t f = (size_t)blockIdx.x * blockDim.x + threadIdx.x;
    if (f >= n4) return;
    int    k4  = (int)(f % Kq);
    size_t row = f / Kq;
    int blk = k4 >> 3;
    int cc  = k4 & 7;
    float4 v = reinterpret_cast<const float4*>(src)[f];
    float* d = dst + row * (size_t)(Kq * 4) + blk * 32 + cc;
    d[0]  = to_tf32(v.x);
    d[8]  = to_tf32(v.y);
    d[16] = to_tf32(v.z);
    d[24] = to_tf32(v.w);
}

// src: [E, R, C] row-major -> dst: [E, C, R] with tf32 rounding and K-perm on R.
__global__ void transpose_rna_perm_kernel(const float* __restrict__ src, float* __restrict__ dst,
                                          int R, int C) {
    __shared__ float tile[32][33];
    const size_t eoff = (size_t)blockIdx.z * R * C;
    const float* s = src + eoff;
    float*       d = dst + eoff;
    int c0 = blockIdx.x * 32;
    int r0 = blockIdx.y * 32;
    int tx = threadIdx.x;
    #pragma unroll
    for (int i = threadIdx.y; i < 32; i += 8)
        tile[i][tx] = s[(size_t)(r0 + i) * C + (c0 + tx)];
    __syncthreads();
    int pp = ((tx & 3) * 8) + (tx >> 2);     // perm within 32-block
    #pragma unroll
    for (int i = threadIdx.y; i < 32; i += 8)
        d[(size_t)(c0 + i) * R + r0 + pp] = to_tf32(tile[tx][i]);
}

// ---------------------------------------------------------------------------
// Grouped GEMM (tf32 mma.sync):  C[e,m,n] = sum_k A[e,m,k]*B[e,n,k] + bias[e,n]
//   A: [E*CAPT, K]  K-perm, tf32-rounded
//   B: [E*Ntot, K]  K-perm, tf32-rounded (pre-transposed weight)
//   GELU_PERM=true : C = tf32(gelu(acc+bias)), stored K-permuted (feeds GEMM2)
//   GELU_PERM=false: C = acc + bias, plain row-major (final output)
// Tile: 256x128x32, 16 warps (64x32 warp tiles, 4x4), 4-stage cp.async
// pipeline, 4 warps/SMSP for latency hiding, <=128 regs/thread.
// ---------------------------------------------------------------------------
template <bool GELU_PERM>
__global__ void __launch_bounds__(THREADS, 1)
grouped_gemm_tf32(const float* __restrict__ A, const float* __restrict__ B,
                  const float* __restrict__ bias, float* __restrict__ Cout,
                  int K, int Ntot) {
    constexpr uint32_t A_BYTES = BM * 128;              // 32 KB (32 floats/row)
    constexpr uint32_t B_BYTES = BN * 128;              // 16 KB
    constexpr uint32_t STAGE_BYTES = A_BYTES + B_BYTES; // 48 KB

    extern __shared__ char dsmem[];
    const uint32_t smem0 = smem_u32(dsmem);

    const int tid  = threadIdx.x;
    const int wid  = tid >> 5;
    const int lane = tid & 31;
    const int wm   = wid & 3;                 // 4 warps along M (64 rows each)
    const int wn   = wid >> 2;                // 4 warps along N (32 cols each)
    const int e  = blockIdx.z;
    const int m0 = blockIdx.x * BM;
    const int n0 = blockIdx.y * BN;

    const float* Abase = A + ((size_t)e * CAPT + m0) * (size_t)K;
    const float* Bbase = B + ((size_t)e * Ntot + n0) * (size_t)K;

    const int nk = K / BK;

    // ---- hoisted per-thread cp.async addressing --------------------------
    // A: 256 rows x 8 chunks(16B) = 2048 chunks, 4 per thread
    // B: 128 rows x 8 chunks = 1024 chunks, 2 per thread
    const float* agp[4];
    const float* bgp[2];
    uint32_t     asw[4];
    uint32_t     bsw[2];
    #pragma unroll
    for (int i = 0; i < 4; i++) {
        int q = i * THREADS + tid;
        int r = q >> 3, c = q & 7;
        asw[i] = (uint32_t)(r * 128 + ((c ^ (r & 7)) << 4));
        agp[i] = Abase + (size_t)r * K + c * 4;
    }
    #pragma unroll
    for (int i = 0; i < 2; i++) {
        int q = i * THREADS + tid;
        int r = q >> 3, c = q & 7;
        bsw[i] = (uint32_t)(A_BYTES + r * 128 + ((c ^ (r & 7)) << 4));
        bgp[i] = Bbase + (size_t)r * K + c * 4;
    }

    auto load_stage = [&](int s) {
        const uint32_t base = smem0 + (uint32_t)(s & (STAGES - 1)) * STAGE_BYTES;
        const int koff = s * BK;
        #pragma unroll
        for (int i = 0; i < 4; i++) cp_async16(base + asw[i], agp[i] + koff);
        #pragma unroll
        for (int i = 0; i < 2; i++) cp_async16(base + bsw[i], bgp[i] + koff);
    };

    // ---- accumulators: warp tile 64x32 = 4 m-tiles x 4 n-tiles ----------
    float acc[4][4][4];
    #pragma unroll
    for (int mt = 0; mt < 4; mt++)
        #pragma unroll
        for (int nt = 0; nt < 4; nt++)
            #pragma unroll
            for (int j = 0; j < 4; j++) acc[mt][nt][j] = 0.0f;

    // prologue: 3 stages in flight
    load_stage(0); cp_commit();
    load_stage(1); cp_commit();
    load_stage(2); cp_commit();

    const int sw = lane >> 2;                  // row mod 8 for this lane
    const uint32_t ch0 = (uint32_t)(((2 * (lane & 3) + 0) ^ sw) << 4);
    const uint32_t ch1 = (uint32_t)(((2 * (lane & 3) + 1) ^ sw) << 4);
    const uint32_t aRowOff = (uint32_t)((wm * 64 + sw) * 128);
    const uint32_t bRowOff = (uint32_t)(A_BYTES + (wn * 32 + sw) * 128);

    #pragma unroll 1
    for (int kt = 0; kt < nk; ++kt) {
        cp_wait_group<STAGES - 2>();       // stage kt resident
        __syncthreads();

        const uint32_t sbase = smem0 + (uint32_t)(kt & (STAGES - 1)) * STAGE_BYTES;
        const uint32_t aB = sbase + aRowOff;
        const uint32_t bB = sbase + bRowOff;

        #pragma unroll
        for (int q = 0; q < 2; ++q) {
            const uint32_t chq = q ? ch1 : ch0;

            // A fragments for all 4 m-tiles (32 regs)
            uint32_t al[4][4], ah[4][4];
            #pragma unroll
            for (int mt = 0; mt < 4; mt++) {
                lds128(aB + mt * 2048 + chq,        al[mt][0], al[mt][1], al[mt][2], al[mt][3]);
                lds128(aB + mt * 2048 + 1024 + chq, ah[mt][0], ah[mt][1], ah[mt][2], ah[mt][3]);
            }

            // next-stage copies issued once per k-tile, off the fragment path
            if (q == 0) {
                if (kt + STAGES - 1 < nk) load_stage(kt + STAGES - 1);
                cp_commit();
            }

            // nt in chunks of 2 (8 B regs live), split k-halves for ILP
            #pragma unroll
            for (int nc = 0; nc < 2; ++nc) {
                uint32_t bv[2][4];
                #pragma unroll
                for (int j = 0; j < 2; j++)
                    lds128(bB + (nc * 2 + j) * 1024 + chq,
                           bv[j][0], bv[j][1], bv[j][2], bv[j][3]);
                #pragma unroll
                for (int j = 0; j < 2; j++)
                    #pragma unroll
                    for (int mt = 0; mt < 4; mt++)
                        mma_tf32(acc[mt][nc * 2 + j],
                                 al[mt][0], ah[mt][0], al[mt][1], ah[mt][1],
                                 bv[j][0], bv[j][1]);
                #pragma unroll
                for (int j = 0; j < 2; j++)
                    #pragma unroll
                    for (int mt = 0; mt < 4; mt++)
                        mma_tf32(acc[mt][nc * 2 + j],
                                 al[mt][2], ah[mt][2], al[mt][3], ah[mt][3],
                                 bv[j][2], bv[j][3]);
            }
        }
    }

    // ---- epilogue --------------------------------------------------------
    const float* bb = bias + (size_t)e * Ntot + n0;
    const int rowbase = m0 + wm * 64;
    const int colbase = wn * 32;               // within-tile col

    #pragma unroll
    for (int mt = 0; mt < 4; mt++) {
        int r = rowbase + mt * 16 + (lane >> 2);
        size_t grow0 = ((size_t)e * CAPT + r) * (size_t)Ntot;
        size_t grow1 = ((size_t)e * CAPT + r + 8) * (size_t)Ntot;
        #pragma unroll
        for (int nt = 0; nt < 4; nt++) {
            int c  = colbase + nt * 8 + 2 * (lane & 3);   // within-tile col
            int gc = n0 + c;
            float b0v = bb[c], b1v = bb[c + 1];
            float v00 = acc[mt][nt][0] + b0v;
            float v01 = acc[mt][nt][1] + b1v;
            float v10 = acc[mt][nt][2] + b0v;
            float v11 = acc[mt][nt][3] + b1v;
            if (GELU_PERM) {
                v00 = to_tf32(gelu_tanh(v00));
                v01 = to_tf32(gelu_tanh(v01));
                v10 = to_tf32(gelu_tanh(v10));
                v11 = to_tf32(gelu_tanh(v11));
                int p0 = kperm(gc), p1 = kperm(gc + 1);
                Cout[grow0 + p0] = v00;
                Cout[grow0 + p1] = v01;
                Cout[grow1 + p0] = v10;
                Cout[grow1 + p1] = v11;
            } else {
                float2 lo = make_float2(v00, v01);
                float2 hi = make_float2(v10, v11);
                *reinterpret_cast<float2*>(Cout + grow0 + gc) = lo;
                *reinterpret_cast<float2*>(Cout + grow1 + gc) = hi;
            }
        }
    }
}

// ---------------------------------------------------------------------------
// Launch
// ---------------------------------------------------------------------------
extern "C" void kernel_launch(void* const* d_in, const int* in_sizes, int n_in,
                              void* d_out, int out_size) {
    (void)in_sizes; (void)n_in; (void)out_size;
    const float* X  = (const float*)d_in[0];
    // d_in[1] = tokens_per_expert (equal capacity; unused)
    const float* W1 = (const float*)d_in[2];
    const float* B1 = (const float*)d_in[3];
    const float* W2 = (const float*)d_in[4];
    const float* B2 = (const float*)d_in[5];
    float* OUT = (float*)d_out;

    float *pX, *pW1t, *pW2t, *pH;
    cudaGetSymbolAddress((void**)&pX,   g_Xr);
    cudaGetSymbolAddress((void**)&pW1t, g_W1t);
    cudaGetSymbolAddress((void**)&pW2t, g_W2t);
    cudaGetSymbolAddress((void**)&pH,   g_H);

    constexpr int SMEM_DYN = STAGES * (BM * 128 + BN * 128);  // 196608 B
    cudaFuncSetAttribute(grouped_gemm_tf32<true>,  cudaFuncAttributeMaxDynamicSharedMemorySize, SMEM_DYN);
    cudaFuncSetAttribute(grouped_gemm_tf32<false>, cudaFuncAttributeMaxDynamicSharedMemorySize, SMEM_DYN);

    // 1) round + K-permute X
    {
        size_t n4 = (size_t)NTOK * HDIM / 4;
        round_permute_kernel<<<(unsigned)((n4 + 255) / 256), 256>>>(X, pX, HDIM / 4, n4);
    }
    // 2) transpose + round + K-permute weights
    {
        dim3 tb(32, 8);
        transpose_rna_perm_kernel<<<dim3(FDIM / 32, HDIM / 32, NE), tb>>>(W1, pW1t, HDIM, FDIM);
        transpose_rna_perm_kernel<<<dim3(HDIM / 32, FDIM / 32, NE), tb>>>(W2, pW2t, FDIM, HDIM);
    }
    // 3) GEMM1 + bias + GELU -> H (tf32, K-perm)
    grouped_gemm_tf32<true><<<dim3(CAPT / BM, FDIM / BN, NE), THREADS, SMEM_DYN>>>(
        pX, pW1t, B1, pH, HDIM, FDIM);
    // 4) GEMM2 + bias -> OUT (plain layout)
    grouped_gemm_tf32<false><<<dim3(CAPT / BM, HDIM / BN, NE), THREADS, SMEM_DYN>>>(
        pH, pW2t, B2, OUT, FDIM, HDIM);
}

// round 7
// speedup vs baseline: 1.6605x; 1.6605x over previous
#include <cuda_runtime.h>
#include <cuda_fp16.h>
#include <cstdint>

// ---------------------------------------------------------------------------
// Problem constants (fixed shapes per reference)
// ---------------------------------------------------------------------------
#define NE   8
#define HDIM 2048
#define FDIM 8192
#define NTOK 16384
#define CAPT (NTOK / NE)   // 2048 tokens per expert

// GEMM tiling
#define BM 128
#define BN 256
#define BK 32          // fp16 elements per k-tile (64 bytes per row)
#define STAGES 4
#define THREADS 256

// ---------------------------------------------------------------------------
// Scratch (static __device__ arrays; no allocation allowed)
// fp16, K-major with a permuted K layout: within each 32-element k-block,
// element k sits at pos = t*8 + blk*4 + half*2 + odd, where
//   t=( (k&15) & 7 )>>1, blk=(k>>4)&1, half=(k&15)>>3, odd=k&1.
// This makes the 16B v4 at byte offset 16*t of a row hold exactly the
// m16n8k16 fragment registers {blk0:(2t,2t+1),(2t+8,2t+9), blk1: same} —
// i.e. one LDS.128 feeds TWO k16 MMAs, with linear (conflict-free) addresses.
// ---------------------------------------------------------------------------
__device__ __align__(16) __half g_Xr [(size_t)NTOK * HDIM];       // 64 MB
__device__ __align__(16) __half g_W1t[(size_t)NE * FDIM * HDIM];  // 256 MB [F,H]
__device__ __align__(16) __half g_W2t[(size_t)NE * HDIM * FDIM];  // 256 MB [H,F]
__device__ __align__(16) __half g_H  [(size_t)NTOK * FDIM];       // 256 MB

// ---------------------------------------------------------------------------
// Helpers
// ---------------------------------------------------------------------------
__device__ __forceinline__ uint32_t smem_u32(const void* p) {
    uint32_t a;
    asm("{ .reg .u64 t; cvta.to.shared.u64 t, %1; cvt.u32.u64 %0, t; }" : "=r"(a) : "l"(p));
    return a;
}

__device__ __forceinline__ void cp_async16(uint32_t smem_dst, const void* gmem_src) {
    asm volatile("cp.async.cg.shared.global [%0], [%1], 16;" :: "r"(smem_dst), "l"(gmem_src) : "memory");
}
__device__ __forceinline__ void cp_commit() {
    asm volatile("cp.async.commit_group;" ::: "memory");
}
template <int N>
__device__ __forceinline__ void cp_wait_group() {
    asm volatile("cp.async.wait_group %0;" :: "n"(N) : "memory");
}

__device__ __forceinline__ void lds128(uint32_t addr, uint32_t& x, uint32_t& y,
                                       uint32_t& z, uint32_t& w) {
    asm volatile("ld.shared.v4.b32 {%0,%1,%2,%3}, [%4];"
                 : "=r"(x), "=r"(y), "=r"(z), "=r"(w) : "r"(addr));
}

// fp16 HMMA m16n8k16, fp32 accumulate (sm_80 baseline; compiles on compute_103)
__device__ __forceinline__ void mma_f16(float* c, uint32_t a0, uint32_t a1,
                                        uint32_t a2, uint32_t a3,
                                        uint32_t b0, uint32_t b1) {
    asm volatile(
        "mma.sync.aligned.m16n8k16.row.col.f32.f16.f16.f32 "
        "{%0,%1,%2,%3}, {%4,%5,%6,%7}, {%8,%9}, {%0,%1,%2,%3};"
        : "+f"(c[0]), "+f"(c[1]), "+f"(c[2]), "+f"(c[3])
        : "r"(a0), "r"(a1), "r"(a2), "r"(a3), "r"(b0), "r"(b1));
}

__device__ __forceinline__ float gelu_tanh(float x) {
    float x3 = x * x * x;
    float u  = 0.7978845608028654f * (x + 0.044715f * x3);
    return 0.5f * x * (1.0f + tanhf(u));
}

// permuted position of (even) k index within the fp16 layout
__device__ __forceinline__ int kperm16_even(int k) {
    int base = k & ~31;
    int kk   = k & 15;
    int blk  = (k >> 4) & 1;
    int t    = (kk & 7) >> 1;
    int half = kk >> 3;
    return base + t * 8 + blk * 4 + half * 2;
}

// ---------------------------------------------------------------------------
// Prep kernels
// ---------------------------------------------------------------------------
// fp32 [rows, K] row-major -> fp16 K-perm. One thread per even k-pair.
__global__ void round_permute_f16_kernel(const float* __restrict__ src,
                                         __half* __restrict__ dst,
                                         int Kh /* K/2 */, size_t n2) {
    size_t f = (size_t)blockIdx.x * blockDim.x + threadIdx.x;
    if (f >= n2) return;
    int    k2  = (int)(f % Kh);
    size_t row = f / Kh;
    int k = 2 * k2;
    float2 v = reinterpret_cast<const float2*>(src)[f];
    __half2 h = __floats2half2_rn(v.x, v.y);
    *reinterpret_cast<__half2*>(dst + row * (size_t)(Kh * 2) + kperm16_even(k)) = h;
}

// src: [E, R, C] fp32 row-major -> dst: [E, C, R] fp16 with K-perm on R.
__global__ void transpose_f16_perm_kernel(const float* __restrict__ src,
                                          __half* __restrict__ dst,
                                          int R, int C) {
    __shared__ float tile[32][33];
    const size_t eoff = (size_t)blockIdx.z * R * C;
    const float*  s = src + eoff;
    __half*       d = dst + eoff;
    int c0 = blockIdx.x * 32;
    int r0 = blockIdx.y * 32;
    int tx = threadIdx.x;
    #pragma unroll
    for (int i = threadIdx.y; i < 32; i += 8)
        tile[i][tx] = s[(size_t)(r0 + i) * C + (c0 + tx)];
    __syncthreads();
    // perm of tx within its 32-block (R is the K dim of the GEMM)
    int kk   = tx & 15;
    int pp   = ((kk & 7) >> 1) * 8 + ((tx >> 4) & 1) * 4 + (kk >> 3) * 2 + (tx & 1);
    #pragma unroll
    for (int i = threadIdx.y; i < 32; i += 8)
        d[(size_t)(c0 + i) * R + r0 + pp] = __float2half_rn(tile[tx][i]);
}

// ---------------------------------------------------------------------------
// Grouped GEMM (fp16 mma.sync, fp32 accum):
//   C[e,m,n] = sum_k A[e,m,k]*B[e,n,k] + bias[e,n]
//   A: [E*CAPT, K] fp16 K-perm;  B: [E*Ntot, K] fp16 K-perm (pre-transposed W)
//   GELU_PERM=true : C = fp16(gelu(acc+bias)) stored K-perm (feeds GEMM2)
//   GELU_PERM=false: C = acc + bias, fp32 row-major (final output)
// Tile 128x256x32, 8 warps (64x64 warp tiles), 4-stage cp.async pipeline.
// All smem addresses are linear per warp -> no swizzle, conflict-free.
// ---------------------------------------------------------------------------
template <bool GELU_PERM>
__global__ void __launch_bounds__(THREADS, 1)
grouped_gemm_f16(const __half* __restrict__ A, const __half* __restrict__ B,
                 const float* __restrict__ bias, void* __restrict__ CoutV,
                 int K, int Ntot) {
    constexpr uint32_t A_BYTES = BM * 64;               // 8 KB
    constexpr uint32_t B_BYTES = BN * 64;               // 16 KB
    constexpr uint32_t STAGE_BYTES = A_BYTES + B_BYTES; // 24 KB

    extern __shared__ char dsmem[];
    const uint32_t smem0 = smem_u32(dsmem);

    const int tid  = threadIdx.x;
    const int wid  = tid >> 5;
    const int lane = tid & 31;
    const int wm   = wid & 1;                 // 2 warps along M (64 rows)
    const int wn   = wid >> 1;                // 4 warps along N (64 cols)
    const int e  = blockIdx.z;
    const int m0 = blockIdx.x * BM;
    const int n0 = blockIdx.y * BN;

    const __half* Abase = A + ((size_t)e * CAPT + m0) * (size_t)K;
    const __half* Bbase = B + ((size_t)e * Ntot + n0) * (size_t)K;

    const int nk = K / BK;

    // ---- hoisted cp.async addressing (all linear, no swizzle) ------------
    // A: 512 x 16B chunks, 2/thread.  B: 1024 chunks, 4/thread.
    const __half* agp[2];
    const __half* bgp[4];
    uint32_t      adst[2], bdst[4];
    #pragma unroll
    for (int i = 0; i < 2; i++) {
        int q = i * THREADS + tid;
        adst[i] = (uint32_t)(q * 16);
        agp[i]  = Abase + (size_t)(q >> 2) * K + (q & 3) * 8;
    }
    #pragma unroll
    for (int i = 0; i < 4; i++) {
        int q = i * THREADS + tid;
        bdst[i] = (uint32_t)(A_BYTES + q * 16);
        bgp[i]  = Bbase + (size_t)(q >> 2) * K + (q & 3) * 8;
    }

    auto load_stage = [&](int s) {
        const uint32_t base = smem0 + (uint32_t)(s & (STAGES - 1)) * STAGE_BYTES;
        const int koff = s * BK;
        #pragma unroll
        for (int i = 0; i < 2; i++) cp_async16(base + adst[i], agp[i] + koff);
        #pragma unroll
        for (int i = 0; i < 4; i++) cp_async16(base + bdst[i], bgp[i] + koff);
    };

    // ---- accumulators: warp tile 64x64 = 4 m-tiles x 8 n-tiles -----------
    float acc[4][8][4];
    #pragma unroll
    for (int mt = 0; mt < 4; mt++)
        #pragma unroll
        for (int nt = 0; nt < 8; nt++)
            #pragma unroll
            for (int j = 0; j < 4; j++) acc[mt][nt][j] = 0.0f;

    load_stage(0); cp_commit();
    load_stage(1); cp_commit();
    load_stage(2); cp_commit();

    const int g = lane >> 2;                   // fragment row group
    const int t = lane & 3;
    // A lo (row g) base: rows are 64B; linear in lane (addr = lane*16 within group)
    const uint32_t aOff = (uint32_t)((wm * 64 + g) * 64 + t * 16);
    const uint32_t bOff = (uint32_t)(A_BYTES + (wn * 64 + g) * 64 + t * 16);

    #pragma unroll 1
    for (int kt = 0; kt < nk; ++kt) {
        cp_wait_group<STAGES - 2>();
        __syncthreads();

        const uint32_t sbase = smem0 + (uint32_t)(kt & (STAGES - 1)) * STAGE_BYTES;
        const uint32_t aB = sbase + aOff;
        const uint32_t bB = sbase + bOff;

        // A fragments: lo = row g (a0/a2 pairs), hi = row g+8 (a1/a3 pairs),
        // each v4 covers BOTH k16 blocks of this k-tile.
        uint32_t lo[4][4], hi[4][4];
        #pragma unroll
        for (int mt = 0; mt < 4; mt++) {
            lds128(aB + mt * 1024,       lo[mt][0], lo[mt][1], lo[mt][2], lo[mt][3]);
            lds128(aB + mt * 1024 + 512, hi[mt][0], hi[mt][1], hi[mt][2], hi[mt][3]);
        }

        if (kt + STAGES - 1 < nk) load_stage(kt + STAGES - 1);
        cp_commit();

        #pragma unroll
        for (int nc = 0; nc < 4; ++nc) {
            uint32_t bv[2][4];
            #pragma unroll
            for (int j = 0; j < 2; j++)
                lds128(bB + (nc * 2 + j) * 512, bv[j][0], bv[j][1], bv[j][2], bv[j][3]);
            // k16 block 0
            #pragma unroll
            for (int j = 0; j < 2; j++)
                #pragma unroll
                for (int mt = 0; mt < 4; mt++)
                    mma_f16(acc[mt][nc * 2 + j],
                            lo[mt][0], hi[mt][0], lo[mt][1], hi[mt][1],
                            bv[j][0], bv[j][1]);
            // k16 block 1
            #pragma unroll
            for (int j = 0; j < 2; j++)
                #pragma unroll
                for (int mt = 0; mt < 4; mt++)
                    mma_f16(acc[mt][nc * 2 + j],
                            lo[mt][2], hi[mt][2], lo[mt][3], hi[mt][3],
                            bv[j][2], bv[j][3]);
        }
    }

    // ---- epilogue ---------------------------------------------------------
    const float* bb = bias + (size_t)e * Ntot + n0;
    const int rowbase = m0 + wm * 64;
    const int colbase = wn * 64;

    #pragma unroll
    for (int mt = 0; mt < 4; mt++) {
        int r = rowbase + mt * 16 + g;
        size_t grow0 = ((size_t)e * CAPT + r) * (size_t)Ntot;
        size_t grow1 = ((size_t)e * CAPT + r + 8) * (size_t)Ntot;
        #pragma unroll
        for (int nt = 0; nt < 8; nt++) {
            int c  = colbase + nt * 8 + 2 * t;
            int gc = n0 + c;
            float b0v = bb[c], b1v = bb[c + 1];
            float v00 = acc[mt][nt][0] + b0v;
            float v01 = acc[mt][nt][1] + b1v;
            float v10 = acc[mt][nt][2] + b0v;
            float v11 = acc[mt][nt][3] + b1v;
            if (GELU_PERM) {
                __half* Cout = (__half*)CoutV;
                __half2 h0 = __floats2half2_rn(gelu_tanh(v00), gelu_tanh(v01));
                __half2 h1 = __floats2half2_rn(gelu_tanh(v10), gelu_tanh(v11));
                int p = kperm16_even(gc);
                *reinterpret_cast<__half2*>(Cout + grow0 + p) = h0;
                *reinterpret_cast<__half2*>(Cout + grow1 + p) = h1;
            } else {
                float* Cout = (float*)CoutV;
                *reinterpret_cast<float2*>(Cout + grow0 + gc) = make_float2(v00, v01);
                *reinterpret_cast<float2*>(Cout + grow1 + gc) = make_float2(v10, v11);
            }
        }
    }
}

// ---------------------------------------------------------------------------
// Launch
// ---------------------------------------------------------------------------
extern "C" void kernel_launch(void* const* d_in, const int* in_sizes, int n_in,
                              void* d_out, int out_size) {
    (void)in_sizes; (void)n_in; (void)out_size;
    const float* X  = (const float*)d_in[0];
    // d_in[1] = tokens_per_expert (equal capacity; unused)
    const float* W1 = (const float*)d_in[2];
    const float* B1 = (const float*)d_in[3];
    const float* W2 = (const float*)d_in[4];
    const float* B2 = (const float*)d_in[5];
    float* OUT = (float*)d_out;

    __half *pX, *pW1t, *pW2t, *pH;
    cudaGetSymbolAddress((void**)&pX,   g_Xr);
    cudaGetSymbolAddress((void**)&pW1t, g_W1t);
    cudaGetSymbolAddress((void**)&pW2t, g_W2t);
    cudaGetSymbolAddress((void**)&pH,   g_H);

    constexpr int SMEM_DYN = STAGES * (BM * 64 + BN * 64);  // 98304 B
    cudaFuncSetAttribute(grouped_gemm_f16<true>,  cudaFuncAttributeMaxDynamicSharedMemorySize, SMEM_DYN);
    cudaFuncSetAttribute(grouped_gemm_f16<false>, cudaFuncAttributeMaxDynamicSharedMemorySize, SMEM_DYN);

    // 1) round + K-permute X -> fp16
    {
        size_t n2 = (size_t)NTOK * HDIM / 2;
        round_permute_f16_kernel<<<(unsigned)((n2 + 255) / 256), 256>>>(X, pX, HDIM / 2, n2);
    }
    // 2) transpose + round + K-permute weights -> fp16
    {
        dim3 tb(32, 8);
        transpose_f16_perm_kernel<<<dim3(FDIM / 32, HDIM / 32, NE), tb>>>(W1, pW1t, HDIM, FDIM);
        transpose_f16_perm_kernel<<<dim3(HDIM / 32, FDIM / 32, NE), tb>>>(W2, pW2t, FDIM, HDIM);
    }
    // 3) GEMM1 + bias + GELU -> H (fp16, K-perm)
    grouped_gemm_f16<true><<<dim3(CAPT / BM, FDIM / BN, NE), THREADS, SMEM_DYN>>>(
        pX, pW1t, B1, pH, HDIM, FDIM);
    // 4) GEMM2 + bias -> OUT (fp32)
    grouped_gemm_f16<false><<<dim3(CAPT / BM, HDIM / BN, NE), THREADS, SMEM_DYN>>>(
        pH, pW2t, B2, OUT, FDIM, HDIM);
}

// round 8
// speedup vs baseline: 1.6750x; 1.0087x over previous
#include <cuda_runtime.h>
#include <cuda_fp16.h>
#include <cstdint>

// ---------------------------------------------------------------------------
// Problem constants (fixed shapes per reference)
// ---------------------------------------------------------------------------
#define NE   8
#define HDIM 2048
#define FDIM 8192
#define NTOK 16384
#define CAPT (NTOK / NE)   // 2048 tokens per expert

// GEMM tiling
#define BM 256
#define BN 128
#define BK 32          // fp16 elements per k-tile (64 bytes per row)
#define STAGES 4
#define THREADS 512

// ---------------------------------------------------------------------------
// Scratch (static __device__ arrays; no allocation allowed)
// fp16, K-major with a permuted K layout: within each 32-element k-block,
// element k sits at pos = t*8 + blk*4 + half*2 + odd, where
//   t=((k&15)&7)>>1, blk=(k>>4)&1, half=(k&15)>>3, odd=k&1.
// One 16B v4 at byte offset 16*t of a row holds exactly the m16n8k16
// fragment registers for BOTH k16 blocks of the 32-k tile, with linear
// (conflict-free) shared-memory addressing. Validated in R7.
// ---------------------------------------------------------------------------
__device__ __align__(16) __half g_Xr [(size_t)NTOK * HDIM];       // 64 MB
__device__ __align__(16) __half g_W1t[(size_t)NE * FDIM * HDIM];  // 256 MB [F,H]
__device__ __align__(16) __half g_W2t[(size_t)NE * HDIM * FDIM];  // 256 MB [H,F]
__device__ __align__(16) __half g_H  [(size_t)NTOK * FDIM];       // 256 MB

// ---------------------------------------------------------------------------
// Helpers
// ---------------------------------------------------------------------------
__device__ __forceinline__ uint32_t smem_u32(const void* p) {
    uint32_t a;
    asm("{ .reg .u64 t; cvta.to.shared.u64 t, %1; cvt.u32.u64 %0, t; }" : "=r"(a) : "l"(p));
    return a;
}

__device__ __forceinline__ void cp_async16(uint32_t smem_dst, const void* gmem_src) {
    asm volatile("cp.async.cg.shared.global [%0], [%1], 16;" :: "r"(smem_dst), "l"(gmem_src) : "memory");
}
__device__ __forceinline__ void cp_commit() {
    asm volatile("cp.async.commit_group;" ::: "memory");
}
template <int N>
__device__ __forceinline__ void cp_wait_group() {
    asm volatile("cp.async.wait_group %0;" :: "n"(N) : "memory");
}

__device__ __forceinline__ void lds128(uint32_t addr, uint32_t& x, uint32_t& y,
                                       uint32_t& z, uint32_t& w) {
    asm volatile("ld.shared.v4.b32 {%0,%1,%2,%3}, [%4];"
                 : "=r"(x), "=r"(y), "=r"(z), "=r"(w) : "r"(addr));
}

// fp16 HMMA m16n8k16, fp32 accumulate (sm_80 baseline; compiles on compute_103)
__device__ __forceinline__ void mma_f16(float* c, uint32_t a0, uint32_t a1,
                                        uint32_t a2, uint32_t a3,
                                        uint32_t b0, uint32_t b1) {
    asm volatile(
        "mma.sync.aligned.m16n8k16.row.col.f32.f16.f16.f32 "
        "{%0,%1,%2,%3}, {%4,%5,%6,%7}, {%8,%9}, {%0,%1,%2,%3};"
        : "+f"(c[0]), "+f"(c[1]), "+f"(c[2]), "+f"(c[3])
        : "r"(a0), "r"(a1), "r"(a2), "r"(a3), "r"(b0), "r"(b1));
}

__device__ __forceinline__ float gelu_tanh(float x) {
    float x3 = x * x * x;
    float u  = 0.7978845608028654f * (x + 0.044715f * x3);
    return 0.5f * x * (1.0f + tanhf(u));
}

// permuted position of (even) k index within the fp16 layout
__device__ __forceinline__ int kperm16_even(int k) {
    int base = k & ~31;
    int kk   = k & 15;
    int blk  = (k >> 4) & 1;
    int t    = (kk & 7) >> 1;
    int half = kk >> 3;
    return base + t * 8 + blk * 4 + half * 2;
}

// ---------------------------------------------------------------------------
// Prep kernels
// ---------------------------------------------------------------------------
// fp32 [rows, K] row-major -> fp16 K-perm. One thread per even k-pair.
__global__ void round_permute_f16_kernel(const float* __restrict__ src,
                                         __half* __restrict__ dst,
                                         int Kh /* K/2 */, size_t n2) {
    size_t f = (size_t)blockIdx.x * blockDim.x + threadIdx.x;
    if (f >= n2) return;
    int    k2  = (int)(f % Kh);
    size_t row = f / Kh;
    int k = 2 * k2;
    float2 v = reinterpret_cast<const float2*>(src)[f];
    __half2 h = __floats2half2_rn(v.x, v.y);
    *reinterpret_cast<__half2*>(dst + row * (size_t)(Kh * 2) + kperm16_even(k)) = h;
}

// src: [E, R, C] fp32 row-major -> dst: [E, C, R] fp16 with K-perm on R.
__global__ void transpose_f16_perm_kernel(const float* __restrict__ src,
                                          __half* __restrict__ dst,
                                          int R, int C) {
    __shared__ float tile[32][33];
    const size_t eoff = (size_t)blockIdx.z * R * C;
    const float*  s = src + eoff;
    __half*       d = dst + eoff;
    int c0 = blockIdx.x * 32;
    int r0 = blockIdx.y * 32;
    int tx = threadIdx.x;
    #pragma unroll
    for (int i = threadIdx.y; i < 32; i += 8)
        tile[i][tx] = s[(size_t)(r0 + i) * C + (c0 + tx)];
    __syncthreads();
    // perm of tx within its 32-block (R is the K dim of the GEMM)
    int kk   = tx & 15;
    int pp   = ((kk & 7) >> 1) * 8 + ((tx >> 4) & 1) * 4 + (kk >> 3) * 2 + (tx & 1);
    #pragma unroll
    for (int i = threadIdx.y; i < 32; i += 8)
        d[(size_t)(c0 + i) * R + r0 + pp] = __float2half_rn(tile[tx][i]);
}

// ---------------------------------------------------------------------------
// Grouped GEMM (fp16 mma.sync, fp32 accum):
//   C[e,m,n] = sum_k A[e,m,k]*B[e,n,k] + bias[e,n]
//   A: [E*CAPT, K] fp16 K-perm;  B: [E*Ntot, K] fp16 K-perm (pre-transposed W)
//   GELU_PERM=true : C = fp16(gelu(acc+bias)) stored K-perm (feeds GEMM2)
//   GELU_PERM=false: C = acc + bias, fp32 row-major (final output)
// Tile 256x128x32, 16 warps (64x32 warp tiles, 4x4), 4-stage cp.async
// pipeline, 4 warps/SMSP, <=128 regs/thread (no spills).
// ---------------------------------------------------------------------------
template <bool GELU_PERM>
__global__ void __launch_bounds__(THREADS, 1)
grouped_gemm_f16(const __half* __restrict__ A, const __half* __restrict__ B,
                 const float* __restrict__ bias, void* __restrict__ CoutV,
                 int K, int Ntot) {
    constexpr uint32_t A_BYTES = BM * 64;               // 16 KB
    constexpr uint32_t B_BYTES = BN * 64;               // 8 KB
    constexpr uint32_t STAGE_BYTES = A_BYTES + B_BYTES; // 24 KB

    extern __shared__ char dsmem[];
    const uint32_t smem0 = smem_u32(dsmem);

    const int tid  = threadIdx.x;
    const int wid  = tid >> 5;
    const int lane = tid & 31;
    const int wm   = wid & 3;                 // 4 warps along M (64 rows)
    const int wn   = wid >> 2;                // 4 warps along N (32 cols)
    const int e  = blockIdx.z;
    const int m0 = blockIdx.x * BM;
    const int n0 = blockIdx.y * BN;

    const __half* Abase = A + ((size_t)e * CAPT + m0) * (size_t)K;
    const __half* Bbase = B + ((size_t)e * Ntot + n0) * (size_t)K;

    const int nk = K / BK;

    // ---- hoisted cp.async addressing (all linear, no swizzle) ------------
    // A: 1024 x 16B chunks, 2/thread.  B: 512 chunks, 1/thread.
    const __half* agp[2];
    const __half* bgp;
    uint32_t      adst[2], bdst;
    #pragma unroll
    for (int i = 0; i < 2; i++) {
        int q = i * THREADS + tid;
        adst[i] = (uint32_t)(q * 16);
        agp[i]  = Abase + (size_t)(q >> 2) * K + (q & 3) * 8;
    }
    {
        int q = tid;
        bdst = (uint32_t)(A_BYTES + q * 16);
        bgp  = Bbase + (size_t)(q >> 2) * K + (q & 3) * 8;
    }

    auto load_stage = [&](int s) {
        const uint32_t base = smem0 + (uint32_t)(s & (STAGES - 1)) * STAGE_BYTES;
        const int koff = s * BK;
        #pragma unroll
        for (int i = 0; i < 2; i++) cp_async16(base + adst[i], agp[i] + koff);
        cp_async16(base + bdst, bgp + koff);
    };

    // ---- accumulators: warp tile 64x32 = 4 m-tiles x 4 n-tiles -----------
    float acc[4][4][4];
    #pragma unroll
    for (int mt = 0; mt < 4; mt++)
        #pragma unroll
        for (int nt = 0; nt < 4; nt++)
            #pragma unroll
            for (int j = 0; j < 4; j++) acc[mt][nt][j] = 0.0f;

    load_stage(0); cp_commit();
    load_stage(1); cp_commit();
    load_stage(2); cp_commit();

    const int g = lane >> 2;                   // fragment row group
    const int t = lane & 3;
    const uint32_t aOff = (uint32_t)((wm * 64 + g) * 64 + t * 16);
    const uint32_t bOff = (uint32_t)(A_BYTES + (wn * 32 + g) * 64 + t * 16);

    #pragma unroll 1
    for (int kt = 0; kt < nk; ++kt) {
        cp_wait_group<STAGES - 2>();
        __syncthreads();

        const uint32_t sbase = smem0 + (uint32_t)(kt & (STAGES - 1)) * STAGE_BYTES;
        const uint32_t aB = sbase + aOff;
        const uint32_t bB = sbase + bOff;

        // All fragment loads up-front: 8 A + 4 B LDS.128, back-to-back.
        uint32_t lo[4][4], hi[4][4];
        #pragma unroll
        for (int mt = 0; mt < 4; mt++) {
            lds128(aB + mt * 1024,       lo[mt][0], lo[mt][1], lo[mt][2], lo[mt][3]);
            lds128(aB + mt * 1024 + 512, hi[mt][0], hi[mt][1], hi[mt][2], hi[mt][3]);
        }
        uint32_t bv[4][4];
        #pragma unroll
        for (int nt = 0; nt < 4; nt++)
            lds128(bB + nt * 512, bv[nt][0], bv[nt][1], bv[nt][2], bv[nt][3]);

        // next-stage copies, off the fragment-load critical path
        if (kt + STAGES - 1 < nk) load_stage(kt + STAGES - 1);
        cp_commit();

        // k16 block 0: 16 independent MMAs
        #pragma unroll
        for (int nt = 0; nt < 4; nt++)
            #pragma unroll
            for (int mt = 0; mt < 4; mt++)
                mma_f16(acc[mt][nt],
                        lo[mt][0], hi[mt][0], lo[mt][1], hi[mt][1],
                        bv[nt][0], bv[nt][1]);
        // k16 block 1: dependent partners are 16 issues away
        #pragma unroll
        for (int nt = 0; nt < 4; nt++)
            #pragma unroll
            for (int mt = 0; mt < 4; mt++)
                mma_f16(acc[mt][nt],
                        lo[mt][2], hi[mt][2], lo[mt][3], hi[mt][3],
                        bv[nt][2], bv[nt][3]);
    }

    // ---- epilogue ---------------------------------------------------------
    const float* bb = bias + (size_t)e * Ntot + n0;
    const int rowbase = m0 + wm * 64;
    const int colbase = wn * 32;

    #pragma unroll
    for (int mt = 0; mt < 4; mt++) {
        int r = rowbase + mt * 16 + g;
        size_t grow0 = ((size_t)e * CAPT + r) * (size_t)Ntot;
        size_t grow1 = ((size_t)e * CAPT + r + 8) * (size_t)Ntot;
        #pragma unroll
        for (int nt = 0; nt < 4; nt++) {
            int c  = colbase + nt * 8 + 2 * t;
            int gc = n0 + c;
            float b0v = bb[c], b1v = bb[c + 1];
            float v00 = acc[mt][nt][0] + b0v;
            float v01 = acc[mt][nt][1] + b1v;
            float v10 = acc[mt][nt][2] + b0v;
            float v11 = acc[mt][nt][3] + b1v;
            if (GELU_PERM) {
                __half* Cout = (__half*)CoutV;
                __half2 h0 = __floats2half2_rn(gelu_tanh(v00), gelu_tanh(v01));
                __half2 h1 = __floats2half2_rn(gelu_tanh(v10), gelu_tanh(v11));
                int p = kperm16_even(gc);
                *reinterpret_cast<__half2*>(Cout + grow0 + p) = h0;
                *reinterpret_cast<__half2*>(Cout + grow1 + p) = h1;
            } else {
                float* Cout = (float*)CoutV;
                *reinterpret_cast<float2*>(Cout + grow0 + gc) = make_float2(v00, v01);
                *reinterpret_cast<float2*>(Cout + grow1 + gc) = make_float2(v10, v11);
            }
        }
    }
}

// ---------------------------------------------------------------------------
// Launch
// ---------------------------------------------------------------------------
extern "C" void kernel_launch(void* const* d_in, const int* in_sizes, int n_in,
                              void* d_out, int out_size) {
    (void)in_sizes; (void)n_in; (void)out_size;
    const float* X  = (const float*)d_in[0];
    // d_in[1] = tokens_per_expert (equal capacity; unused)
    const float* W1 = (const float*)d_in[2];
    const float* B1 = (const float*)d_in[3];
    const float* W2 = (const float*)d_in[4];
    const float* B2 = (const float*)d_in[5];
    float* OUT = (float*)d_out;

    __half *pX, *pW1t, *pW2t, *pH;
    cudaGetSymbolAddress((void**)&pX,   g_Xr);
    cudaGetSymbolAddress((void**)&pW1t, g_W1t);
    cudaGetSymbolAddress((void**)&pW2t, g_W2t);
    cudaGetSymbolAddress((void**)&pH,   g_H);

    constexpr int SMEM_DYN = STAGES * (BM * 64 + BN * 64);  // 98304 B
    cudaFuncSetAttribute(grouped_gemm_f16<true>,  cudaFuncAttributeMaxDynamicSharedMemorySize, SMEM_DYN);
    cudaFuncSetAttribute(grouped_gemm_f16<false>, cudaFuncAttributeMaxDynamicSharedMemorySize, SMEM_DYN);

    // 1) round + K-permute X -> fp16
    {
        size_t n2 = (size_t)NTOK * HDIM / 2;
        round_permute_f16_kernel<<<(unsigned)((n2 + 255) / 256), 256>>>(X, pX, HDIM / 2, n2);
    }
    // 2) transpose + round + K-permute weights -> fp16
    {
        dim3 tb(32, 8);
        transpose_f16_perm_kernel<<<dim3(FDIM / 32, HDIM / 32, NE), tb>>>(W1, pW1t, HDIM, FDIM);
        transpose_f16_perm_kernel<<<dim3(HDIM / 32, FDIM / 32, NE), tb>>>(W2, pW2t, FDIM, HDIM);
    }
    // 3) GEMM1 + bias + GELU -> H (fp16, K-perm)
    grouped_gemm_f16<true><<<dim3(CAPT / BM, FDIM / BN, NE), THREADS, SMEM_DYN>>>(
        pX, pW1t, B1, pH, HDIM, FDIM);
    // 4) GEMM2 + bias -> OUT (fp32)
    grouped_gemm_f16<false><<<dim3(CAPT / BM, HDIM / BN, NE), THREADS, SMEM_DYN>>>(
        pH, pW2t, B2, OUT, FDIM, HDIM);
}

// round 9
// speedup vs baseline: 1.6867x; 1.0070x over previous
#include <cuda_runtime.h>
#include <cuda_fp16.h>
#include <cstdint>

// ---------------------------------------------------------------------------
// Problem constants (fixed shapes per reference)
// ---------------------------------------------------------------------------
#define NE   8
#define HDIM 2048
#define FDIM 8192
#define NTOK 16384
#define CAPT (NTOK / NE)   // 2048 tokens per expert

// GEMM tiling
#define BM 128
#define BN 128
#define BK 32          // fp16 elements per k-tile (64 bytes per row)
#define STAGES 4
#define THREADS 256

// ---------------------------------------------------------------------------
// Scratch (static __device__ arrays; no allocation allowed)
// fp16, K-major with a permuted K layout: within each 32-element k-block,
// element k sits at pos = t*8 + blk*4 + half*2 + odd, where
//   t=((k&15)&7)>>1, blk=(k>>4)&1, half=(k&15)>>3, odd=k&1.
// One 16B v4 at byte offset 16*t of a row holds exactly the m16n8k16
// fragment registers for BOTH k16 blocks of the 32-k tile, with linear
// (conflict-free) shared-memory addressing. Validated in R7/R8.
// ---------------------------------------------------------------------------
__device__ __align__(16) __half g_Xr [(size_t)NTOK * HDIM];       // 64 MB
__device__ __align__(16) __half g_W1t[(size_t)NE * FDIM * HDIM];  // 256 MB [F,H]
__device__ __align__(16) __half g_W2t[(size_t)NE * HDIM * FDIM];  // 256 MB [H,F]
__device__ __align__(16) __half g_H  [(size_t)NTOK * FDIM];       // 256 MB

// ---------------------------------------------------------------------------
// Helpers
// ---------------------------------------------------------------------------
__device__ __forceinline__ uint32_t smem_u32(const void* p) {
    uint32_t a;
    asm("{ .reg .u64 t; cvta.to.shared.u64 t, %1; cvt.u32.u64 %0, t; }" : "=r"(a) : "l"(p));
    return a;
}

__device__ __forceinline__ void cp_async16(uint32_t smem_dst, const void* gmem_src) {
    asm volatile("cp.async.cg.shared.global [%0], [%1], 16;" :: "r"(smem_dst), "l"(gmem_src) : "memory");
}
__device__ __forceinline__ void cp_commit() {
    asm volatile("cp.async.commit_group;" ::: "memory");
}
template <int N>
__device__ __forceinline__ void cp_wait_group() {
    asm volatile("cp.async.wait_group %0;" :: "n"(N) : "memory");
}

__device__ __forceinline__ void lds128(uint32_t addr, uint32_t& x, uint32_t& y,
                                       uint32_t& z, uint32_t& w) {
    asm volatile("ld.shared.v4.b32 {%0,%1,%2,%3}, [%4];"
                 : "=r"(x), "=r"(y), "=r"(z), "=r"(w) : "r"(addr));
}

// fp16 HMMA m16n8k16, fp32 accumulate (sm_80 baseline; compiles on compute_103)
__device__ __forceinline__ void mma_f16(float* c, uint32_t a0, uint32_t a1,
                                        uint32_t a2, uint32_t a3,
                                        uint32_t b0, uint32_t b1) {
    asm volatile(
        "mma.sync.aligned.m16n8k16.row.col.f32.f16.f16.f32 "
        "{%0,%1,%2,%3}, {%4,%5,%6,%7}, {%8,%9}, {%0,%1,%2,%3};"
        : "+f"(c[0]), "+f"(c[1]), "+f"(c[2]), "+f"(c[3])
        : "r"(a0), "r"(a1), "r"(a2), "r"(a3), "r"(b0), "r"(b1));
}

__device__ __forceinline__ float gelu_tanh(float x) {
    float x3 = x * x * x;
    float u  = 0.7978845608028654f * (x + 0.044715f * x3);
    return 0.5f * x * (1.0f + tanhf(u));
}

// permuted position of (even) k index within the fp16 layout
__device__ __forceinline__ int kperm16_even(int k) {
    int base = k & ~31;
    int kk   = k & 15;
    int blk  = (k >> 4) & 1;
    int t    = (kk & 7) >> 1;
    int half = kk >> 3;
    return base + t * 8 + blk * 4 + half * 2;
}

// ---------------------------------------------------------------------------
// Prep kernels
// ---------------------------------------------------------------------------
// fp32 [rows, K] row-major -> fp16 K-perm. One thread per even k-pair.
__global__ void round_permute_f16_kernel(const float* __restrict__ src,
                                         __half* __restrict__ dst,
                                         int Kh /* K/2 */, size_t n2) {
    size_t f = (size_t)blockIdx.x * blockDim.x + threadIdx.x;
    if (f >= n2) return;
    int    k2  = (int)(f % Kh);
    size_t row = f / Kh;
    int k = 2 * k2;
    float2 v = reinterpret_cast<const float2*>(src)[f];
    __half2 h = __floats2half2_rn(v.x, v.y);
    *reinterpret_cast<__half2*>(dst + row * (size_t)(Kh * 2) + kperm16_even(k)) = h;
}

// src: [E, R, C] fp32 row-major -> dst: [E, C, R] fp16 with K-perm on R.
__global__ void transpose_f16_perm_kernel(const float* __restrict__ src,
                                          __half* __restrict__ dst,
                                          int R, int C) {
    __shared__ float tile[32][33];
    const size_t eoff = (size_t)blockIdx.z * R * C;
    const float*  s = src + eoff;
    __half*       d = dst + eoff;
    int c0 = blockIdx.x * 32;
    int r0 = blockIdx.y * 32;
    int tx = threadIdx.x;
    #pragma unroll
    for (int i = threadIdx.y; i < 32; i += 8)
        tile[i][tx] = s[(size_t)(r0 + i) * C + (c0 + tx)];
    __syncthreads();
    // perm of tx within its 32-block (R is the K dim of the GEMM)
    int kk   = tx & 15;
    int pp   = ((kk & 7) >> 1) * 8 + ((tx >> 4) & 1) * 4 + (kk >> 3) * 2 + (tx & 1);
    #pragma unroll
    for (int i = threadIdx.y; i < 32; i += 8)
        d[(size_t)(c0 + i) * R + r0 + pp] = __float2half_rn(tile[tx][i]);
}

// ---------------------------------------------------------------------------
// Grouped GEMM (fp16 mma.sync, fp32 accum):
//   C[e,m,n] = sum_k A[e,m,k]*B[e,n,k] + bias[e,n]
//   A: [E*CAPT, K] fp16 K-perm;  B: [E*Ntot, K] fp16 K-perm (pre-transposed W)
//   GELU_PERM=true : C = fp16(gelu(acc+bias)) stored K-perm (feeds GEMM2)
//   GELU_PERM=false: C = acc + bias, fp32 row-major (final output)
// Tile 128x128x32, 8 warps (64x32 warp tiles, 2x4), 4-stage cp.async pipeline.
// TWO CTAs per SM (__launch_bounds__(256,2), 64 KB smem each) so the two
// blocks' load/MMA phases interleave instead of lockstepping on one barrier.
// ---------------------------------------------------------------------------
template <bool GELU_PERM>
__global__ void __launch_bounds__(THREADS, 2)
grouped_gemm_f16(const __half* __restrict__ A, const __half* __restrict__ B,
                 const float* __restrict__ bias, void* __restrict__ CoutV,
                 int K, int Ntot) {
    constexpr uint32_t A_BYTES = BM * 64;               // 8 KB
    constexpr uint32_t B_BYTES = BN * 64;               // 8 KB
    constexpr uint32_t STAGE_BYTES = A_BYTES + B_BYTES; // 16 KB

    extern __shared__ char dsmem[];
    const uint32_t smem0 = smem_u32(dsmem);

    const int tid  = threadIdx.x;
    const int wid  = tid >> 5;
    const int lane = tid & 31;
    const int wm   = wid & 1;                 // 2 warps along M (64 rows)
    const int wn   = wid >> 1;                // 4 warps along N (32 cols)
    const int e  = blockIdx.z;
    const int m0 = blockIdx.x * BM;
    const int n0 = blockIdx.y * BN;

    const __half* Abase = A + ((size_t)e * CAPT + m0) * (size_t)K;
    const __half* Bbase = B + ((size_t)e * Ntot + n0) * (size_t)K;

    const int nk = K / BK;

    // ---- hoisted cp.async addressing (all linear, no swizzle) ------------
    // A: 512 x 16B chunks, 2/thread.  B: 512 chunks, 2/thread.
    const __half* agp[2];
    const __half* bgp[2];
    uint32_t      adst[2], bdst[2];
    #pragma unroll
    for (int i = 0; i < 2; i++) {
        int q = i * THREADS + tid;
        adst[i] = (uint32_t)(q * 16);
        agp[i]  = Abase + (size_t)(q >> 2) * K + (q & 3) * 8;
        bdst[i] = (uint32_t)(A_BYTES + q * 16);
        bgp[i]  = Bbase + (size_t)(q >> 2) * K + (q & 3) * 8;
    }

    auto load_stage = [&](int s) {
        const uint32_t base = smem0 + (uint32_t)(s & (STAGES - 1)) * STAGE_BYTES;
        const int koff = s * BK;
        #pragma unroll
        for (int i = 0; i < 2; i++) {
            cp_async16(base + adst[i], agp[i] + koff);
            cp_async16(base + bdst[i], bgp[i] + koff);
        }
    };

    // ---- accumulators: warp tile 64x32 = 4 m-tiles x 4 n-tiles -----------
    float acc[4][4][4];
    #pragma unroll
    for (int mt = 0; mt < 4; mt++)
        #pragma unroll
        for (int nt = 0; nt < 4; nt++)
            #pragma unroll
            for (int j = 0; j < 4; j++) acc[mt][nt][j] = 0.0f;

    load_stage(0); cp_commit();
    load_stage(1); cp_commit();
    load_stage(2); cp_commit();

    const int g = lane >> 2;                   // fragment row group
    const int t = lane & 3;
    const uint32_t aOff = (uint32_t)((wm * 64 + g) * 64 + t * 16);
    const uint32_t bOff = (uint32_t)(A_BYTES + (wn * 32 + g) * 64 + t * 16);

    #pragma unroll 1
    for (int kt = 0; kt < nk; ++kt) {
        cp_wait_group<STAGES - 2>();
        __syncthreads();

        const uint32_t sbase = smem0 + (uint32_t)(kt & (STAGES - 1)) * STAGE_BYTES;
        const uint32_t aB = sbase + aOff;
        const uint32_t bB = sbase + bOff;

        // All fragment loads up-front: 8 A + 4 B LDS.128, back-to-back.
        uint32_t lo[4][4], hi[4][4];
        #pragma unroll
        for (int mt = 0; mt < 4; mt++) {
            lds128(aB + mt * 1024,       lo[mt][0], lo[mt][1], lo[mt][2], lo[mt][3]);
            lds128(aB + mt * 1024 + 512, hi[mt][0], hi[mt][1], hi[mt][2], hi[mt][3]);
        }
        uint32_t bv[4][4];
        #pragma unroll
        for (int nt = 0; nt < 4; nt++)
            lds128(bB + nt * 512, bv[nt][0], bv[nt][1], bv[nt][2], bv[nt][3]);

        // next-stage copies, off the fragment-load critical path
        if (kt + STAGES - 1 < nk) load_stage(kt + STAGES - 1);
        cp_commit();

        // k16 block 0: 16 independent MMAs
        #pragma unroll
        for (int nt = 0; nt < 4; nt++)
            #pragma unroll
            for (int mt = 0; mt < 4; mt++)
                mma_f16(acc[mt][nt],
                        lo[mt][0], hi[mt][0], lo[mt][1], hi[mt][1],
                        bv[nt][0], bv[nt][1]);
        // k16 block 1: dependent partners are 16 issues away
        #pragma unroll
        for (int nt = 0; nt < 4; nt++)
            #pragma unroll
            for (int mt = 0; mt < 4; mt++)
                mma_f16(acc[mt][nt],
                        lo[mt][2], hi[mt][2], lo[mt][3], hi[mt][3],
                        bv[nt][2], bv[nt][3]);
    }

    // ---- epilogue ---------------------------------------------------------
    const float* bb = bias + (size_t)e * Ntot + n0;
    const int rowbase = m0 + wm * 64;
    const int colbase = wn * 32;

    #pragma unroll
    for (int mt = 0; mt < 4; mt++) {
        int r = rowbase + mt * 16 + g;
        size_t grow0 = ((size_t)e * CAPT + r) * (size_t)Ntot;
        size_t grow1 = ((size_t)e * CAPT + r + 8) * (size_t)Ntot;
        #pragma unroll
        for (int nt = 0; nt < 4; nt++) {
            int c  = colbase + nt * 8 + 2 * t;
            int gc = n0 + c;
            float b0v = bb[c], b1v = bb[c + 1];
            float v00 = acc[mt][nt][0] + b0v;
            float v01 = acc[mt][nt][1] + b1v;
            float v10 = acc[mt][nt][2] + b0v;
            float v11 = acc[mt][nt][3] + b1v;
            if (GELU_PERM) {
                __half* Cout = (__half*)CoutV;
                __half2 h0 = __floats2half2_rn(gelu_tanh(v00), gelu_tanh(v01));
                __half2 h1 = __floats2half2_rn(gelu_tanh(v10), gelu_tanh(v11));
                int p = kperm16_even(gc);
                *reinterpret_cast<__half2*>(Cout + grow0 + p) = h0;
                *reinterpret_cast<__half2*>(Cout + grow1 + p) = h1;
            } else {
                float* Cout = (float*)CoutV;
                *reinterpret_cast<float2*>(Cout + grow0 + gc) = make_float2(v00, v01);
                *reinterpret_cast<float2*>(Cout + grow1 + gc) = make_float2(v10, v11);
            }
        }
    }
}

// ---------------------------------------------------------------------------
// Launch
// ---------------------------------------------------------------------------
extern "C" void kernel_launch(void* const* d_in, const int* in_sizes, int n_in,
                              void* d_out, int out_size) {
    (void)in_sizes; (void)n_in; (void)out_size;
    const float* X  = (const float*)d_in[0];
    // d_in[1] = tokens_per_expert (equal capacity; unused)
    const float* W1 = (const float*)d_in[2];
    const float* B1 = (const float*)d_in[3];
    const float* W2 = (const float*)d_in[4];
    const float* B2 = (const float*)d_in[5];
    float* OUT = (float*)d_out;

    __half *pX, *pW1t, *pW2t, *pH;
    cudaGetSymbolAddress((void**)&pX,   g_Xr);
    cudaGetSymbolAddress((void**)&pW1t, g_W1t);
    cudaGetSymbolAddress((void**)&pW2t, g_W2t);
    cudaGetSymbolAddress((void**)&pH,   g_H);

    constexpr int SMEM_DYN = STAGES * (BM * 64 + BN * 64);  // 65536 B
    cudaFuncSetAttribute(grouped_gemm_f16<true>,  cudaFuncAttributeMaxDynamicSharedMemorySize, SMEM_DYN);
    cudaFuncSetAttribute(grouped_gemm_f16<false>, cudaFuncAttributeMaxDynamicSharedMemorySize, SMEM_DYN);

    // 1) round + K-permute X -> fp16
    {
        size_t n2 = (size_t)NTOK * HDIM / 2;
        round_permute_f16_kernel<<<(unsigned)((n2 + 255) / 256), 256>>>(X, pX, HDIM / 2, n2);
    }
    // 2) transpose + round + K-permute weights -> fp16
    {
        dim3 tb(32, 8);
        transpose_f16_perm_kernel<<<dim3(FDIM / 32, HDIM / 32, NE), tb>>>(W1, pW1t, HDIM, FDIM);
        transpose_f16_perm_kernel<<<dim3(HDIM / 32, FDIM / 32, NE), tb>>>(W2, pW2t, FDIM, HDIM);
    }
    // 3) GEMM1 + bias + GELU -> H (fp16, K-perm)
    grouped_gemm_f16<true><<<dim3(CAPT / BM, FDIM / BN, NE), THREADS, SMEM_DYN>>>(
        pX, pW1t, B1, pH, HDIM, FDIM);
    // 4) GEMM2 + bias -> OUT (fp32)
    grouped_gemm_f16<false><<<dim3(CAPT / BM, HDIM / BN, NE), THREADS, SMEM_DYN>>>(
        pH, pW2t, B2, OUT, FDIM, HDIM);
}